// round 14
// baseline (speedup 1.0000x reference)
#include <cuda_runtime.h>
#include <cuda_bf16.h>
#include <cstdint>
#include <cstddef>

#define Nn   100000
#define Ed   1600000
#define INC  128
#define HC   256
#define LC   64
#define EPSB 1e-5f
#define SCAN_NB ((Nn + 1023) / 1024)   /* 98 */

// ===================== pack helper (weights only) ============================
__device__ __forceinline__ uint32_t pack2(float v) {
    __nv_bfloat16 h = __float2bfloat16(v);
    float hf = __bfloat162float(h);
    __nv_bfloat16 l = __float2bfloat16(v - hf);
    return (uint32_t)__bfloat16_as_ushort(h) | ((uint32_t)__bfloat16_as_ushort(l) << 16);
}

// ===================== scratch (device globals) ==============================
__device__ float    g_bufA[(size_t)Nn * HC];     // fp32 GEMM output
__device__ float    g_bufB[(size_t)Nn * HC];     // fp32 agg/BN staging
__device__ float    g_zbuf[(size_t)Nn * LC];
__device__ uint32_t g_wsplit[229376];            // all 6 weights, transposed+split
__device__ float    g_dinv[Nn];
__device__ int      g_cnt[Nn];
__device__ int      g_rowstart[Nn + 1];
__device__ int      g_wr[Nn];
__device__ int      g_col[Ed];
__device__ int      g_partial[SCAN_NB];
__device__ float    g_bnsum[4 * HC];             // 4 BN stat sets
__device__ float    g_bnsumsq[4 * HC];
__device__ float    g_scale[HC];
__device__ float    g_shift[HC];
__device__ int      g_is32;

// weight-split offsets within g_wsplit (u32 elems, layout [N][K])
#define WOFF_1 0        /* 256x128 */
#define WOFF_2 32768    /* 256x256 */
#define WOFF_3 98304    /* 64x256  */
#define WOFF_4 114688   /* 256x64  */
#define WOFF_5 131072   /* 256x256 */
#define WOFF_6 196608   /* 128x256 */

// ===================== edge dtype detection / CSR build ======================
__global__ void k_detect(const long long* __restrict__ ei64) {
    __shared__ int s_bad;
    if (threadIdx.x == 0) s_bad = 0;
    __syncthreads();
    long long v0 = ei64[threadIdx.x];
    long long v1 = ei64[(size_t)Ed + threadIdx.x];
    if (v0 < 0 || v0 >= (long long)Nn || v1 < 0 || v1 >= (long long)Nn) atomicOr(&s_bad, 1);
    __syncthreads();
    if (threadIdx.x == 0) g_is32 = s_bad ? 1 : 0;
}

__device__ __forceinline__ int edge_at(const void* ei, int is32, size_t pos) {
    if (is32) return ((const int*)ei)[pos];
    return (int)((const long long*)ei)[pos];
}

__global__ void k_zero_all(int* cnt, float* bnsum, float* bnsumsq) {
    int i = blockIdx.x * blockDim.x + threadIdx.x;
    if (i < Nn) cnt[i] = 0;
    if (i < 4 * HC) { bnsum[i] = 0.f; bnsumsq[i] = 0.f; }
}

__global__ void k_hist(const void* __restrict__ ei, int* __restrict__ cnt) {
    int e = blockIdx.x * blockDim.x + threadIdx.x;
    if (e >= Ed) return;
    int dst = edge_at(ei, g_is32, (size_t)Ed + e);
    if ((unsigned)dst < (unsigned)Nn) atomicAdd(&cnt[dst], 1);
}

// ---- parallel 3-phase exclusive scan (+dinv fused into phase 3) -------------
__global__ void __launch_bounds__(1024) k_blocksum(const int* __restrict__ cnt,
                                                   int* __restrict__ partial) {
    int i = blockIdx.x * 1024 + threadIdx.x;
    int v = (i < Nn) ? cnt[i] : 0;
    for (int o = 16; o; o >>= 1) v += __shfl_down_sync(0xFFFFFFFFu, v, o);
    __shared__ int ws[32];
    if ((threadIdx.x & 31) == 0) ws[threadIdx.x >> 5] = v;
    __syncthreads();
    if (threadIdx.x < 32) {
        int t = ws[threadIdx.x];
        for (int o = 16; o; o >>= 1) t += __shfl_down_sync(0xFFFFFFFFu, t, o);
        if (threadIdx.x == 0) partial[blockIdx.x] = t;
    }
}

__global__ void k_scanpartial(int* __restrict__ partial, int* __restrict__ rowlast) {
    if (threadIdx.x == 0) {
        int run = 0;
        for (int b = 0; b < SCAN_NB; ++b) {
            int t = partial[b];
            partial[b] = run;
            run += t;
        }
        rowlast[0] = (run <= Ed) ? run : Ed;
    }
}

__global__ void __launch_bounds__(1024) k_scanlocal(const int* __restrict__ cnt,
                                                    const int* __restrict__ partial,
                                                    int* __restrict__ rowstart,
                                                    int* __restrict__ wr,
                                                    float* __restrict__ dinv) {
    int i = blockIdx.x * 1024 + threadIdx.x;
    int v = (i < Nn) ? cnt[i] : 0;
    int lane = threadIdx.x & 31, w = threadIdx.x >> 5;
    int incl = v;
    for (int o = 1; o < 32; o <<= 1) {
        int t = __shfl_up_sync(0xFFFFFFFFu, incl, o);
        if (lane >= o) incl += t;
    }
    __shared__ int ws[32];
    if (lane == 31) ws[w] = incl;
    __syncthreads();
    if (threadIdx.x < 32) {
        int t = ws[threadIdx.x];
        int sc = t;
        for (int o = 1; o < 32; o <<= 1) {
            int u = __shfl_up_sync(0xFFFFFFFFu, sc, o);
            if (threadIdx.x >= o) sc += u;
        }
        ws[threadIdx.x] = sc - t;   // exclusive warp offset
    }
    __syncthreads();
    int excl = incl - v + ws[w] + partial[blockIdx.x];
    if (i < Nn) {
        rowstart[i] = excl;
        wr[i] = excl;
        dinv[i] = rsqrtf((float)(v + 1));
    }
}

__global__ void k_scatter(const void* __restrict__ ei,
                          int* __restrict__ wr, int* __restrict__ col) {
    int e = blockIdx.x * blockDim.x + threadIdx.x;
    if (e >= Ed) return;
    int is32 = g_is32;
    int src = edge_at(ei, is32, (size_t)e);
    int dst = edge_at(ei, is32, (size_t)Ed + e);
    if ((unsigned)dst >= (unsigned)Nn || (unsigned)src >= (unsigned)Nn) return;
    int pos = atomicAdd(&wr[dst], 1);
    if ((unsigned)pos < (unsigned)Ed) col[pos] = src;
}

// ===================== weight transpose + split (one launch) =================
__global__ void k_wsplit_all(const float* W1, const float* W2, const float* W3,
                             const float* W4, const float* W5, const float* W6,
                             uint32_t* __restrict__ out) {
    int idx = blockIdx.x * blockDim.x + threadIdx.x;
    const float* W;
    int K, N, base;
    if (idx < 32768)        { W = W1; K = INC; N = HC;  base = 0;      }
    else if (idx < 98304)   { W = W2; K = HC;  N = HC;  base = 32768;  }
    else if (idx < 114688)  { W = W3; K = HC;  N = LC;  base = 98304;  }
    else if (idx < 131072)  { W = W4; K = LC;  N = HC;  base = 114688; }
    else if (idx < 196608)  { W = W5; K = HC;  N = HC;  base = 131072; }
    else if (idx < 229376)  { W = W6; K = HC;  N = INC; base = 196608; }
    else return;
    int local = idx - base;
    int k = local / N, n = local % N;
    out[(size_t)base + (size_t)n * K + k] = pack2(W[local]);
}

// ===================== aggregations (one warp per node, unrolled) ============
__global__ void __launch_bounds__(256) k_agg128(const float* __restrict__ h,
                                                const int* __restrict__ rowstart,
                                                const int* __restrict__ col,
                                                const float* __restrict__ dinv,
                                                float* __restrict__ outp) {
    int warp = (blockIdx.x * blockDim.x + threadIdx.x) >> 5;
    int lane = threadIdx.x & 31;
    if (warp >= Nn) return;
    float di = dinv[warp];
    int jb = rowstart[warp], je = rowstart[warp + 1];
    const float4* h4 = (const float4*)h;  // 32 float4 per row
    float cs = di * di;
    float4 x = h4[(size_t)warp * 32 + lane];
    float4 a = make_float4(cs * x.x, cs * x.y, cs * x.z, cs * x.w);
    int j = jb;
    for (; j + 4 <= je; j += 4) {
        int s0 = col[j], s1 = col[j + 1], s2 = col[j + 2], s3 = col[j + 3];
        float c0 = di * dinv[s0], c1 = di * dinv[s1];
        float c2 = di * dinv[s2], c3 = di * dinv[s3];
        float4 y0 = h4[(size_t)s0 * 32 + lane];
        float4 y1 = h4[(size_t)s1 * 32 + lane];
        float4 y2 = h4[(size_t)s2 * 32 + lane];
        float4 y3 = h4[(size_t)s3 * 32 + lane];
        a.x += c0 * y0.x + c1 * y1.x + c2 * y2.x + c3 * y3.x;
        a.y += c0 * y0.y + c1 * y1.y + c2 * y2.y + c3 * y3.y;
        a.z += c0 * y0.z + c1 * y1.z + c2 * y2.z + c3 * y3.z;
        a.w += c0 * y0.w + c1 * y1.w + c2 * y2.w + c3 * y3.w;
    }
    for (; j < je; ++j) {
        int s = col[j];
        float c = di * dinv[s];
        float4 y = h4[(size_t)s * 32 + lane];
        a.x += c * y.x; a.y += c * y.y; a.z += c * y.z; a.w += c * y.w;
    }
    ((float4*)outp)[(size_t)warp * 32 + lane] = a;
}

__global__ void __launch_bounds__(256) k_agg256_bn(const float* __restrict__ h,
                                                   const int* __restrict__ rowstart,
                                                   const int* __restrict__ col,
                                                   const float* __restrict__ dinv,
                                                   const float* __restrict__ scale,
                                                   const float* __restrict__ shift,
                                                   float* __restrict__ outp) {
    int warp = (blockIdx.x * blockDim.x + threadIdx.x) >> 5;
    int lane = threadIdx.x & 31;
    if (warp >= Nn) return;
    float di = dinv[warp];
    int jb = rowstart[warp], je = rowstart[warp + 1];
    const float4* h4 = (const float4*)h;  // 64 float4 per row
    int f0 = lane, f1 = lane + 32;
    float4 sc0 = ((const float4*)scale)[f0], sh0 = ((const float4*)shift)[f0];
    float4 sc1 = ((const float4*)scale)[f1], sh1 = ((const float4*)shift)[f1];
    float cs = di * di;
    float4 a0, a1;
    {
        float4 x0 = h4[(size_t)warp * 64 + f0];
        float4 x1 = h4[(size_t)warp * 64 + f1];
        a0.x = cs * fmaxf(fmaf(x0.x, sc0.x, sh0.x), 0.f);
        a0.y = cs * fmaxf(fmaf(x0.y, sc0.y, sh0.y), 0.f);
        a0.z = cs * fmaxf(fmaf(x0.z, sc0.z, sh0.z), 0.f);
        a0.w = cs * fmaxf(fmaf(x0.w, sc0.w, sh0.w), 0.f);
        a1.x = cs * fmaxf(fmaf(x1.x, sc1.x, sh1.x), 0.f);
        a1.y = cs * fmaxf(fmaf(x1.y, sc1.y, sh1.y), 0.f);
        a1.z = cs * fmaxf(fmaf(x1.z, sc1.z, sh1.z), 0.f);
        a1.w = cs * fmaxf(fmaf(x1.w, sc1.w, sh1.w), 0.f);
    }
    int j = jb;
    for (; j + 2 <= je; j += 2) {
        int s0 = col[j], s1 = col[j + 1];
        float c0 = di * dinv[s0], c1 = di * dinv[s1];
        float4 p0 = h4[(size_t)s0 * 64 + f0];
        float4 p1 = h4[(size_t)s0 * 64 + f1];
        float4 q0 = h4[(size_t)s1 * 64 + f0];
        float4 q1 = h4[(size_t)s1 * 64 + f1];
        a0.x += c0 * fmaxf(fmaf(p0.x, sc0.x, sh0.x), 0.f) + c1 * fmaxf(fmaf(q0.x, sc0.x, sh0.x), 0.f);
        a0.y += c0 * fmaxf(fmaf(p0.y, sc0.y, sh0.y), 0.f) + c1 * fmaxf(fmaf(q0.y, sc0.y, sh0.y), 0.f);
        a0.z += c0 * fmaxf(fmaf(p0.z, sc0.z, sh0.z), 0.f) + c1 * fmaxf(fmaf(q0.z, sc0.z, sh0.z), 0.f);
        a0.w += c0 * fmaxf(fmaf(p0.w, sc0.w, sh0.w), 0.f) + c1 * fmaxf(fmaf(q0.w, sc0.w, sh0.w), 0.f);
        a1.x += c0 * fmaxf(fmaf(p1.x, sc1.x, sh1.x), 0.f) + c1 * fmaxf(fmaf(q1.x, sc1.x, sh1.x), 0.f);
        a1.y += c0 * fmaxf(fmaf(p1.y, sc1.y, sh1.y), 0.f) + c1 * fmaxf(fmaf(q1.y, sc1.y, sh1.y), 0.f);
        a1.z += c0 * fmaxf(fmaf(p1.z, sc1.z, sh1.z), 0.f) + c1 * fmaxf(fmaf(q1.z, sc1.z, sh1.z), 0.f);
        a1.w += c0 * fmaxf(fmaf(p1.w, sc1.w, sh1.w), 0.f) + c1 * fmaxf(fmaf(q1.w, sc1.w, sh1.w), 0.f);
    }
    for (; j < je; ++j) {
        int s = col[j];
        float c = di * dinv[s];
        float4 y0 = h4[(size_t)s * 64 + f0];
        float4 y1 = h4[(size_t)s * 64 + f1];
        a0.x += c * fmaxf(fmaf(y0.x, sc0.x, sh0.x), 0.f);
        a0.y += c * fmaxf(fmaf(y0.y, sc0.y, sh0.y), 0.f);
        a0.z += c * fmaxf(fmaf(y0.z, sc0.z, sh0.z), 0.f);
        a0.w += c * fmaxf(fmaf(y0.w, sc0.w, sh0.w), 0.f);
        a1.x += c * fmaxf(fmaf(y1.x, sc1.x, sh1.x), 0.f);
        a1.y += c * fmaxf(fmaf(y1.y, sc1.y, sh1.y), 0.f);
        a1.z += c * fmaxf(fmaf(y1.z, sc1.z, sh1.z), 0.f);
        a1.w += c * fmaxf(fmaf(y1.w, sc1.w, sh1.w), 0.f);
    }
    ((float4*)outp)[(size_t)warp * 64 + f0] = a0;
    ((float4*)outp)[(size_t)warp * 64 + f1] = a1;
}

__global__ void __launch_bounds__(256) k_agg_z64(const float* __restrict__ h,
                                                 const int* __restrict__ rowstart,
                                                 const int* __restrict__ col,
                                                 const float* __restrict__ dinv,
                                                 const float* __restrict__ bias,
                                                 float* __restrict__ zout) {
    int warp = (blockIdx.x * blockDim.x + threadIdx.x) >> 5;
    int lane = threadIdx.x & 31;
    if (warp >= Nn) return;
    float di = dinv[warp];
    int jb = rowstart[warp], je = rowstart[warp + 1];
    const float2* h2 = (const float2*)h;  // 32 float2 per row
    float cs = di * di;
    float2 x = h2[(size_t)warp * 32 + lane];
    float2 a = make_float2(cs * x.x, cs * x.y);
    int j = jb;
    for (; j + 4 <= je; j += 4) {
        int s0 = col[j], s1 = col[j + 1], s2 = col[j + 2], s3 = col[j + 3];
        float c0 = di * dinv[s0], c1 = di * dinv[s1];
        float c2 = di * dinv[s2], c3 = di * dinv[s3];
        float2 y0 = h2[(size_t)s0 * 32 + lane];
        float2 y1 = h2[(size_t)s1 * 32 + lane];
        float2 y2 = h2[(size_t)s2 * 32 + lane];
        float2 y3 = h2[(size_t)s3 * 32 + lane];
        a.x += c0 * y0.x + c1 * y1.x + c2 * y2.x + c3 * y3.x;
        a.y += c0 * y0.y + c1 * y1.y + c2 * y2.y + c3 * y3.y;
    }
    for (; j < je; ++j) {
        int s = col[j];
        float c = di * dinv[s];
        float2 y = h2[(size_t)s * 32 + lane];
        a.x += c * y.x; a.y += c * y.y;
    }
    float2 b = *(const float2*)(bias + lane * 2);
    a.x += b.x; a.y += b.y;
    ((float2*)zout)[(size_t)warp * 32 + lane] = a;
}

// ===================== BatchNorm finalize (stats fused into GEMM) ============
__global__ void k_bn_finalize(const float* __restrict__ sum, const float* __restrict__ sumsq,
                              const float* __restrict__ gamma, const float* __restrict__ beta,
                              float* __restrict__ scale, float* __restrict__ shift) {
    int c = threadIdx.x;
    float invM = 1.f / (float)Nn;
    float m = sum[c] * invM;
    float v = fmaxf(sumsq[c] * invM - m * m, 0.f);
    float sc = gamma[c] * rsqrtf(v + EPSB);
    scale[c] = sc;
    shift[c] = beta[c] - m * sc;
}

// ===================== mma.sync bf16 GEMM (3-pass hi/lo, reg prefetch) =======
__device__ __forceinline__ void mma16816(float* acc, const uint32_t* a, const uint32_t* b) {
    asm volatile(
        "mma.sync.aligned.m16n8k16.row.col.f32.bf16.bf16.f32 "
        "{%0,%1,%2,%3}, {%4,%5,%6,%7}, {%8,%9}, {%0,%1,%2,%3};"
        : "+f"(acc[0]), "+f"(acc[1]), "+f"(acc[2]), "+f"(acc[3])
        : "r"(a[0]), "r"(a[1]), "r"(a[2]), "r"(a[3]), "r"(b[0]), "r"(b[1]));
}

template <int KT, int NT, bool HAS_BIAS, bool STATS, bool BNA>
__global__ void __launch_bounds__(256, 2) k_mma(const float* __restrict__ A,
                                                const uint32_t* __restrict__ Bp,
                                                const float* __restrict__ bias,
                                                float* __restrict__ C,
                                                float* __restrict__ bnsum,
                                                float* __restrict__ bnsumsq,
                                                const float* __restrict__ scaleA,
                                                const float* __restrict__ shiftA) {
    constexpr int M = Nn;
    constexpr int NCH = KT / 32;
    __shared__ __nv_bfloat16 Ahi[128][40];
    __shared__ __nv_bfloat16 Alo[128][40];
    __shared__ __nv_bfloat16 Bhi[64][40];
    __shared__ __nv_bfloat16 Blo[64][40];

    int tid = threadIdx.x;
    int wid = tid >> 5, lane = tid & 31;
    int g = lane >> 2, tig = lane & 3;
    int warp_m = wid & 3, warp_n = wid >> 2;
    int bm = blockIdx.y * 128, bn = blockIdx.x * 64;

    const int rA = tid >> 1;
    const int koffA = (tid & 1) * 16;
    const bool validA = (bm + rA) < M;
    const int nB = tid >> 2;
    const int koffB = (tid & 3) * 8;

    float acc[2][4][4];
#pragma unroll
    for (int mt = 0; mt < 2; ++mt)
#pragma unroll
        for (int nt = 0; nt < 4; ++nt)
#pragma unroll
            for (int i = 0; i < 4; ++i) acc[mt][nt][i] = 0.f;

    float va[16];
    uint32_t vb[8];

    // ---- prefetch chunk 0 into registers
    {
        if (validA) {
            const float4* src = (const float4*)(A + (size_t)(bm + rA) * KT + koffA);
#pragma unroll
            for (int q = 0; q < 4; ++q) *(float4*)&va[q * 4] = src[q];
        } else {
#pragma unroll
            for (int q = 0; q < 16; ++q) va[q] = 0.f;
        }
        const uint4* srcB = (const uint4*)(Bp + (size_t)(bn + nB) * KT + koffB);
        uint4 v0 = srcB[0], v1 = srcB[1];
        vb[0] = v0.x; vb[1] = v0.y; vb[2] = v0.z; vb[3] = v0.w;
        vb[4] = v1.x; vb[5] = v1.y; vb[6] = v1.z; vb[7] = v1.w;
    }

    for (int ch = 0; ch < NCH; ++ch) {
        const int k0 = ch * 32;
        // ---- store staged registers to smem (BN? + hi/lo split for A)
        {
            float v[16];
#pragma unroll
            for (int q = 0; q < 16; ++q) v[q] = va[q];
            if (BNA) {
                const float4* scp = (const float4*)(scaleA + k0 + koffA);
                const float4* shp = (const float4*)(shiftA + k0 + koffA);
#pragma unroll
                for (int q = 0; q < 4; ++q) {
                    float4 sc = scp[q], sh = shp[q];
                    v[q * 4 + 0] = fmaxf(fmaf(v[q * 4 + 0], sc.x, sh.x), 0.f);
                    v[q * 4 + 1] = fmaxf(fmaf(v[q * 4 + 1], sc.y, sh.y), 0.f);
                    v[q * 4 + 2] = fmaxf(fmaf(v[q * 4 + 2], sc.z, sh.z), 0.f);
                    v[q * 4 + 3] = fmaxf(fmaf(v[q * 4 + 3], sc.w, sh.w), 0.f);
                }
            }
#pragma unroll
            for (int i = 0; i < 16; i += 2) {
                __nv_bfloat16 h0 = __float2bfloat16(v[i]);
                __nv_bfloat16 h1 = __float2bfloat16(v[i + 1]);
                __nv_bfloat16 l0 = __float2bfloat16(v[i] - __bfloat162float(h0));
                __nv_bfloat16 l1 = __float2bfloat16(v[i + 1] - __bfloat162float(h1));
                *(uint32_t*)&Ahi[rA][koffA + i] =
                    (uint32_t)__bfloat16_as_ushort(h0) | ((uint32_t)__bfloat16_as_ushort(h1) << 16);
                *(uint32_t*)&Alo[rA][koffA + i] =
                    (uint32_t)__bfloat16_as_ushort(l0) | ((uint32_t)__bfloat16_as_ushort(l1) << 16);
            }
#pragma unroll
            for (int i = 0; i < 8; i += 2) {
                uint32_t p0 = vb[i], p1 = vb[i + 1];
                *(uint32_t*)&Bhi[nB][koffB + i] = (p0 & 0xFFFFu) | (p1 << 16);
                *(uint32_t*)&Blo[nB][koffB + i] = (p0 >> 16) | (p1 & 0xFFFF0000u);
            }
        }
        __syncthreads();

        // ---- prefetch next chunk (overlaps MMA phase)
        if (ch + 1 < NCH) {
            const int k1 = (ch + 1) * 32;
            if (validA) {
                const float4* src = (const float4*)(A + (size_t)(bm + rA) * KT + k1 + koffA);
#pragma unroll
                for (int q = 0; q < 4; ++q) *(float4*)&va[q * 4] = src[q];
            }
            const uint4* srcB = (const uint4*)(Bp + (size_t)(bn + nB) * KT + k1 + koffB);
            uint4 v0 = srcB[0], v1 = srcB[1];
            vb[0] = v0.x; vb[1] = v0.y; vb[2] = v0.z; vb[3] = v0.w;
            vb[4] = v1.x; vb[5] = v1.y; vb[6] = v1.z; vb[7] = v1.w;
        }

        // ---- MMA phase
#pragma unroll
        for (int kk = 0; kk < 32; kk += 16) {
            uint32_t ah[2][4], al[2][4], bh[4][2], bl[4][2];
            int cA = kk + tig * 2;
#pragma unroll
            for (int mt = 0; mt < 2; ++mt) {
                int r0 = warp_m * 32 + mt * 16 + g;
                ah[mt][0] = *(const uint32_t*)&Ahi[r0][cA];
                ah[mt][1] = *(const uint32_t*)&Ahi[r0 + 8][cA];
                ah[mt][2] = *(const uint32_t*)&Ahi[r0][cA + 8];
                ah[mt][3] = *(const uint32_t*)&Ahi[r0 + 8][cA + 8];
                al[mt][0] = *(const uint32_t*)&Alo[r0][cA];
                al[mt][1] = *(const uint32_t*)&Alo[r0 + 8][cA];
                al[mt][2] = *(const uint32_t*)&Alo[r0][cA + 8];
                al[mt][3] = *(const uint32_t*)&Alo[r0 + 8][cA + 8];
            }
#pragma unroll
            for (int nt = 0; nt < 4; ++nt) {
                int n0 = warp_n * 32 + nt * 8 + g;
                bh[nt][0] = *(const uint32_t*)&Bhi[n0][cA];
                bh[nt][1] = *(const uint32_t*)&Bhi[n0][cA + 8];
                bl[nt][0] = *(const uint32_t*)&Blo[n0][cA];
                bl[nt][1] = *(const uint32_t*)&Blo[n0][cA + 8];
            }
#pragma unroll
            for (int mt = 0; mt < 2; ++mt)
#pragma unroll
                for (int nt = 0; nt < 4; ++nt) {
                    mma16816(acc[mt][nt], ah[mt], bh[nt]);
                    mma16816(acc[mt][nt], ah[mt], bl[nt]);
                    mma16816(acc[mt][nt], al[mt], bh[nt]);
                }
        }
        __syncthreads();
    }

    // ---- epilogue: write C (+bias)
#pragma unroll
    for (int mt = 0; mt < 2; ++mt) {
        int r0 = bm + warp_m * 32 + mt * 16 + g;
#pragma unroll
        for (int nt = 0; nt < 4; ++nt) {
            int cc = bn + warp_n * 32 + nt * 8 + tig * 2;
            float b0 = 0.f, b1 = 0.f;
            if (HAS_BIAS) { b0 = bias[cc]; b1 = bias[cc + 1]; }
            if (r0 < M) {
                float2 v = make_float2(acc[mt][nt][0] + b0, acc[mt][nt][1] + b1);
                *(float2*)(C + (size_t)r0 * NT + cc) = v;
            }
            if (r0 + 8 < M) {
                float2 v = make_float2(acc[mt][nt][2] + b0, acc[mt][nt][3] + b1);
                *(float2*)(C + (size_t)(r0 + 8) * NT + cc) = v;
            }
        }
    }

    // ---- fused BN statistics
    if (STATS) {
#pragma unroll
        for (int nt = 0; nt < 4; ++nt) {
            float s0 = 0.f, s1 = 0.f, q0 = 0.f, q1 = 0.f;
#pragma unroll
            for (int mt = 0; mt < 2; ++mt) {
                int r0 = bm + warp_m * 32 + mt * 16 + g;
                if (r0 < M) {
                    float v0 = acc[mt][nt][0], v1 = acc[mt][nt][1];
                    s0 += v0; q0 += v0 * v0;
                    s1 += v1; q1 += v1 * v1;
                }
                if (r0 + 8 < M) {
                    float v0 = acc[mt][nt][2], v1 = acc[mt][nt][3];
                    s0 += v0; q0 += v0 * v0;
                    s1 += v1; q1 += v1 * v1;
                }
            }
#pragma unroll
            for (int o = 4; o < 32; o <<= 1) {
                s0 += __shfl_xor_sync(0xFFFFFFFFu, s0, o);
                s1 += __shfl_xor_sync(0xFFFFFFFFu, s1, o);
                q0 += __shfl_xor_sync(0xFFFFFFFFu, q0, o);
                q1 += __shfl_xor_sync(0xFFFFFFFFu, q1, o);
            }
            if (lane < 4) {
                int cc = bn + warp_n * 32 + nt * 8 + lane * 2;
                atomicAdd(&bnsum[cc], s0);
                atomicAdd(&bnsum[cc + 1], s1);
                atomicAdd(&bnsumsq[cc], q0);
                atomicAdd(&bnsumsq[cc + 1], q1);
            }
        }
    }
}

// ===================== host orchestration ====================================
template <int KT, int NT, bool HAS_BIAS, bool STATS, bool BNA>
static void launch_mma(const float* A, const uint32_t* Bp, const float* bias,
                       float* C, float* bnsum, float* bnsumsq,
                       const float* scaleA, const float* shiftA) {
    dim3 grid(NT / 64, (Nn + 127) / 128);
    k_mma<KT, NT, HAS_BIAS, STATS, BNA><<<grid, 256>>>(A, Bp, bias, C, bnsum, bnsumsq,
                                                       scaleA, shiftA);
}

extern "C" void kernel_launch(void* const* d_in, const int* in_sizes, int n_in,
                              void* d_out, int out_size) {
    const float* x  = (const float*)d_in[0];
    const void*  ei = d_in[1];
    const float* W1 = (const float*)d_in[2];
    const float* g1 = (const float*)d_in[4];
    const float* be1 = (const float*)d_in[5];
    const float* W2 = (const float*)d_in[6];
    const float* g2 = (const float*)d_in[8];
    const float* be2 = (const float*)d_in[9];
    const float* W3 = (const float*)d_in[10];
    const float* b3 = (const float*)d_in[11];
    const float* dW1 = (const float*)d_in[12];
    const float* dg1 = (const float*)d_in[14];
    const float* dbe1 = (const float*)d_in[15];
    const float* dW2 = (const float*)d_in[16];
    const float* dg2 = (const float*)d_in[18];
    const float* dbe2 = (const float*)d_in[19];
    const float* dW3 = (const float*)d_in[20];
    const float* db3 = (const float*)d_in[21];

    float* out  = (float*)d_out;
    float* xhat = out;                           // [Nn, INC]
    float* zout = out + (size_t)Nn * INC;        // [Nn, LC]

    float *bufA, *bufB, *zbuf, *dinv, *bnsum, *bnsumsq, *fscale, *fshift;
    uint32_t *wsp;
    int *cnt, *rowstart, *wr, *colarr, *partial;
    cudaGetSymbolAddress((void**)&bufA, g_bufA);
    cudaGetSymbolAddress((void**)&bufB, g_bufB);
    cudaGetSymbolAddress((void**)&zbuf, g_zbuf);
    cudaGetSymbolAddress((void**)&wsp, g_wsplit);
    cudaGetSymbolAddress((void**)&dinv, g_dinv);
    cudaGetSymbolAddress((void**)&cnt, g_cnt);
    cudaGetSymbolAddress((void**)&rowstart, g_rowstart);
    cudaGetSymbolAddress((void**)&wr, g_wr);
    cudaGetSymbolAddress((void**)&colarr, g_col);
    cudaGetSymbolAddress((void**)&partial, g_partial);
    cudaGetSymbolAddress((void**)&bnsum, g_bnsum);
    cudaGetSymbolAddress((void**)&bnsumsq, g_bnsumsq);
    cudaGetSymbolAddress((void**)&fscale, g_scale);
    cudaGetSymbolAddress((void**)&fshift, g_shift);

    // ---- edge dtype detection + zero + CSR build (parallel scan, dinv fused) ----
    k_detect<<<1, 256>>>((const long long*)ei);
    k_zero_all<<<(Nn + 255) / 256, 256>>>(cnt, bnsum, bnsumsq);
    k_hist<<<(Ed + 255) / 256, 256>>>(ei, cnt);
    k_blocksum<<<SCAN_NB, 1024>>>(cnt, partial);
    k_scanpartial<<<1, 32>>>(partial, rowstart + Nn);
    k_scanlocal<<<SCAN_NB, 1024>>>(cnt, partial, rowstart, wr, dinv);
    k_scatter<<<(Ed + 255) / 256, 256>>>(ei, wr, colarr);

    // ---- weight transpose + split (one launch) ----
    k_wsplit_all<<<(229376 + 255) / 256, 256>>>(W1, W2, W3, dW1, dW2, dW3, wsp);

    const int aggBlocks = (Nn * 32 + 255) / 256;

    // ---- encoder layer 1:  raw1 = agg(x) @ W1 ; stats0 ----
    k_agg128<<<aggBlocks, 256>>>(x, rowstart, colarr, dinv, bufB);
    launch_mma<INC, HC, false, true, false>(bufB, wsp + WOFF_1, nullptr, bufA,
                                            bnsum, bnsumsq, nullptr, nullptr);
    k_bn_finalize<<<1, HC>>>(bnsum, bnsumsq, g1, be1, fscale, fshift);

    // ---- encoder layer 2:  raw2 = agg(BNrelu(raw1)) @ W2 ; stats1 ----
    k_agg256_bn<<<aggBlocks, 256>>>(bufA, rowstart, colarr, dinv, fscale, fshift, bufB);
    launch_mma<HC, HC, false, true, false>(bufB, wsp + WOFF_2, nullptr, bufA,
                                           bnsum + HC, bnsumsq + HC, nullptr, nullptr);
    k_bn_finalize<<<1, HC>>>(bnsum + HC, bnsumsq + HC, g2, be2, fscale, fshift);

    // ---- encoder layer 3:  z = agg( BNrelu(raw2) @ W3 ) + b3 ----
    launch_mma<HC, LC, false, false, true>(bufA, wsp + WOFF_3, nullptr, zbuf,
                                           nullptr, nullptr, fscale, fshift);
    k_agg_z64<<<aggBlocks, 256>>>(zbuf, rowstart, colarr, dinv, b3, zout);

    // ---- decoder ----
    launch_mma<LC, HC, false, true, false>(zout, wsp + WOFF_4, nullptr, bufA,
                                           bnsum + 2 * HC, bnsumsq + 2 * HC, nullptr, nullptr);
    k_bn_finalize<<<1, HC>>>(bnsum + 2 * HC, bnsumsq + 2 * HC, dg1, dbe1, fscale, fshift);

    launch_mma<HC, HC, false, true, true>(bufA, wsp + WOFF_5, nullptr, bufB,
                                          bnsum + 3 * HC, bnsumsq + 3 * HC, fscale, fshift);
    k_bn_finalize<<<1, HC>>>(bnsum + 3 * HC, bnsumsq + 3 * HC, dg2, dbe2, fscale, fshift);

    launch_mma<HC, INC, true, false, true>(bufB, wsp + WOFF_6, db3, xhat,
                                           nullptr, nullptr, fscale, fshift);
}

// round 16
// speedup vs baseline: 1.0428x; 1.0428x over previous
#include <cuda_runtime.h>
#include <cuda_bf16.h>
#include <cstdint>
#include <cstddef>

#define Nn   100000
#define Ed   1600000
#define INC  128
#define HC   256
#define LC   64
#define EPSB 1e-5f
#define SCAN_NB ((Nn + 1023) / 1024)   /* 98 */

// ===================== pack helper (weights only) ============================
__device__ __forceinline__ uint32_t pack2(float v) {
    __nv_bfloat16 h = __float2bfloat16(v);
    float hf = __bfloat162float(h);
    __nv_bfloat16 l = __float2bfloat16(v - hf);
    return (uint32_t)__bfloat16_as_ushort(h) | ((uint32_t)__bfloat16_as_ushort(l) << 16);
}

// ===================== scratch (device globals) ==============================
__device__ float    g_bufA[(size_t)Nn * HC];     // fp32 GEMM output
__device__ float    g_bufB[(size_t)Nn * HC];     // fp32 agg/BN staging
__device__ float    g_zbuf[(size_t)Nn * LC];
__device__ uint32_t g_wsplit[229376];            // all 6 weights, transposed+split
__device__ float    g_dinv[Nn];
__device__ int      g_cnt[Nn];
__device__ int      g_rowstart[Nn + 1];
__device__ int      g_wr[Nn];
__device__ int      g_col[Ed];
__device__ int      g_partial[SCAN_NB];
__device__ float    g_bnsum[4 * HC];             // 4 BN stat sets
__device__ float    g_bnsumsq[4 * HC];
__device__ int      g_is32;

// weight-split offsets within g_wsplit (u32 elems, layout [N][K])
#define WOFF_1 0        /* 256x128 */
#define WOFF_2 32768    /* 256x256 */
#define WOFF_3 98304    /* 64x256  */
#define WOFF_4 114688   /* 256x64  */
#define WOFF_5 131072   /* 256x256 */
#define WOFF_6 196608   /* 128x256 */

// ===================== zero + edge dtype detection (merged) ==================
__device__ __forceinline__ int edge_at(const void* ei, int is32, size_t pos) {
    if (is32) return ((const int*)ei)[pos];
    return (int)((const long long*)ei)[pos];
}

__global__ void k_zero_detect(int* cnt, float* bnsum, float* bnsumsq,
                              const long long* __restrict__ ei64) {
    int i = blockIdx.x * blockDim.x + threadIdx.x;
    if (i < Nn) cnt[i] = 0;
    if (i < 4 * HC) { bnsum[i] = 0.f; bnsumsq[i] = 0.f; }
    if (blockIdx.x == 0) {
        __shared__ int s_bad;
        if (threadIdx.x == 0) s_bad = 0;
        __syncthreads();
        long long v0 = ei64[threadIdx.x];
        long long v1 = ei64[(size_t)Ed + threadIdx.x];
        if (v0 < 0 || v0 >= (long long)Nn || v1 < 0 || v1 >= (long long)Nn)
            atomicOr(&s_bad, 1);
        __syncthreads();
        if (threadIdx.x == 0) g_is32 = s_bad ? 1 : 0;
    }
}

__global__ void k_hist(const void* __restrict__ ei, int* __restrict__ cnt) {
    int e = blockIdx.x * blockDim.x + threadIdx.x;
    if (e >= Ed) return;
    int dst = edge_at(ei, g_is32, (size_t)Ed + e);
    if ((unsigned)dst < (unsigned)Nn) atomicAdd(&cnt[dst], 1);
}

// ---- parallel 3-phase exclusive scan (+dinv fused into phase 3) -------------
__global__ void __launch_bounds__(1024) k_blocksum(const int* __restrict__ cnt,
                                                   int* __restrict__ partial) {
    int i = blockIdx.x * 1024 + threadIdx.x;
    int v = (i < Nn) ? cnt[i] : 0;
    for (int o = 16; o; o >>= 1) v += __shfl_down_sync(0xFFFFFFFFu, v, o);
    __shared__ int ws[32];
    if ((threadIdx.x & 31) == 0) ws[threadIdx.x >> 5] = v;
    __syncthreads();
    if (threadIdx.x < 32) {
        int t = ws[threadIdx.x];
        for (int o = 16; o; o >>= 1) t += __shfl_down_sync(0xFFFFFFFFu, t, o);
        if (threadIdx.x == 0) partial[blockIdx.x] = t;
    }
}

__global__ void k_scanpartial(int* __restrict__ partial, int* __restrict__ rowlast) {
    if (threadIdx.x == 0) {
        int run = 0;
        for (int b = 0; b < SCAN_NB; ++b) {
            int t = partial[b];
            partial[b] = run;
            run += t;
        }
        rowlast[0] = (run <= Ed) ? run : Ed;
    }
}

__global__ void __launch_bounds__(1024) k_scanlocal(const int* __restrict__ cnt,
                                                    const int* __restrict__ partial,
                                                    int* __restrict__ rowstart,
                                                    int* __restrict__ wr,
                                                    float* __restrict__ dinv) {
    int i = blockIdx.x * 1024 + threadIdx.x;
    int v = (i < Nn) ? cnt[i] : 0;
    int lane = threadIdx.x & 31, w = threadIdx.x >> 5;
    int incl = v;
    for (int o = 1; o < 32; o <<= 1) {
        int t = __shfl_up_sync(0xFFFFFFFFu, incl, o);
        if (lane >= o) incl += t;
    }
    __shared__ int ws[32];
    if (lane == 31) ws[w] = incl;
    __syncthreads();
    if (threadIdx.x < 32) {
        int t = ws[threadIdx.x];
        int sc = t;
        for (int o = 1; o < 32; o <<= 1) {
            int u = __shfl_up_sync(0xFFFFFFFFu, sc, o);
            if (threadIdx.x >= o) sc += u;
        }
        ws[threadIdx.x] = sc - t;   // exclusive warp offset
    }
    __syncthreads();
    int excl = incl - v + ws[w] + partial[blockIdx.x];
    if (i < Nn) {
        rowstart[i] = excl;
        wr[i] = excl;
        dinv[i] = rsqrtf((float)(v + 1));
    }
}

__global__ void k_scatter(const void* __restrict__ ei,
                          int* __restrict__ wr, int* __restrict__ col) {
    int e = blockIdx.x * blockDim.x + threadIdx.x;
    if (e >= Ed) return;
    int is32 = g_is32;
    int src = edge_at(ei, is32, (size_t)e);
    int dst = edge_at(ei, is32, (size_t)Ed + e);
    if ((unsigned)dst >= (unsigned)Nn || (unsigned)src >= (unsigned)Nn) return;
    int pos = atomicAdd(&wr[dst], 1);
    if ((unsigned)pos < (unsigned)Ed) col[pos] = src;
}

// ===================== weight transpose + split (one launch) =================
__global__ void k_wsplit_all(const float* W1, const float* W2, const float* W3,
                             const float* W4, const float* W5, const float* W6,
                             uint32_t* __restrict__ out) {
    int idx = blockIdx.x * blockDim.x + threadIdx.x;
    const float* W;
    int K, N, base;
    if (idx < 32768)        { W = W1; K = INC; N = HC;  base = 0;      }
    else if (idx < 98304)   { W = W2; K = HC;  N = HC;  base = 32768;  }
    else if (idx < 114688)  { W = W3; K = HC;  N = LC;  base = 98304;  }
    else if (idx < 131072)  { W = W4; K = LC;  N = HC;  base = 114688; }
    else if (idx < 196608)  { W = W5; K = HC;  N = HC;  base = 131072; }
    else if (idx < 229376)  { W = W6; K = HC;  N = INC; base = 196608; }
    else return;
    int local = idx - base;
    int k = local / N, n = local % N;
    out[(size_t)base + (size_t)n * K + k] = pack2(W[local]);
}

// ===================== aggregations (one warp per node, simple loops) ========
__global__ void __launch_bounds__(256) k_agg128(const float* __restrict__ h,
                                                const int* __restrict__ rowstart,
                                                const int* __restrict__ col,
                                                const float* __restrict__ dinv,
                                                float* __restrict__ outp) {
    int warp = (blockIdx.x * blockDim.x + threadIdx.x) >> 5;
    int lane = threadIdx.x & 31;
    if (warp >= Nn) return;
    float di = dinv[warp];
    int jb = rowstart[warp], je = rowstart[warp + 1];
    const float4* h4 = (const float4*)h;  // 32 float4 per row
    float cs = di * di;
    float4 x = h4[(size_t)warp * 32 + lane];
    float4 a = make_float4(cs * x.x, cs * x.y, cs * x.z, cs * x.w);
    for (int j = jb; j < je; ++j) {
        int s = col[j];
        float c = di * dinv[s];
        float4 y = h4[(size_t)s * 32 + lane];
        a.x += c * y.x; a.y += c * y.y; a.z += c * y.z; a.w += c * y.w;
    }
    ((float4*)outp)[(size_t)warp * 32 + lane] = a;
}

// agg over BNrelu rows, width 256; BN finalize computed inline from raw stats
__global__ void __launch_bounds__(256) k_agg256_bn(const float* __restrict__ h,
                                                   const int* __restrict__ rowstart,
                                                   const int* __restrict__ col,
                                                   const float* __restrict__ dinv,
                                                   const float* __restrict__ bnsum,
                                                   const float* __restrict__ bnsumsq,
                                                   const float* __restrict__ gamma,
                                                   const float* __restrict__ beta,
                                                   float* __restrict__ outp) {
    __shared__ float s_sc[HC], s_sh[HC];
    {
        int c = threadIdx.x;                     // 256 threads, HC = 256
        float invM = 1.f / (float)Nn;
        float m = bnsum[c] * invM;
        float var = fmaxf(bnsumsq[c] * invM - m * m, 0.f);
        float sc = gamma[c] * rsqrtf(var + EPSB);
        s_sc[c] = sc;
        s_sh[c] = beta[c] - m * sc;
    }
    __syncthreads();

    int warp = (blockIdx.x * blockDim.x + threadIdx.x) >> 5;
    int lane = threadIdx.x & 31;
    if (warp >= Nn) return;
    float di = dinv[warp];
    int jb = rowstart[warp], je = rowstart[warp + 1];
    const float4* h4 = (const float4*)h;  // 64 float4 per row
    int f0 = lane, f1 = lane + 32;
    float4 sc0 = *(const float4*)&s_sc[f0 * 4], sh0 = *(const float4*)&s_sh[f0 * 4];
    float4 sc1 = *(const float4*)&s_sc[f1 * 4], sh1 = *(const float4*)&s_sh[f1 * 4];
    float cs = di * di;
    float4 a0, a1;
    {
        float4 x0 = h4[(size_t)warp * 64 + f0];
        float4 x1 = h4[(size_t)warp * 64 + f1];
        a0.x = cs * fmaxf(fmaf(x0.x, sc0.x, sh0.x), 0.f);
        a0.y = cs * fmaxf(fmaf(x0.y, sc0.y, sh0.y), 0.f);
        a0.z = cs * fmaxf(fmaf(x0.z, sc0.z, sh0.z), 0.f);
        a0.w = cs * fmaxf(fmaf(x0.w, sc0.w, sh0.w), 0.f);
        a1.x = cs * fmaxf(fmaf(x1.x, sc1.x, sh1.x), 0.f);
        a1.y = cs * fmaxf(fmaf(x1.y, sc1.y, sh1.y), 0.f);
        a1.z = cs * fmaxf(fmaf(x1.z, sc1.z, sh1.z), 0.f);
        a1.w = cs * fmaxf(fmaf(x1.w, sc1.w, sh1.w), 0.f);
    }
    for (int j = jb; j < je; ++j) {
        int s = col[j];
        float c = di * dinv[s];
        float4 y0 = h4[(size_t)s * 64 + f0];
        float4 y1 = h4[(size_t)s * 64 + f1];
        a0.x += c * fmaxf(fmaf(y0.x, sc0.x, sh0.x), 0.f);
        a0.y += c * fmaxf(fmaf(y0.y, sc0.y, sh0.y), 0.f);
        a0.z += c * fmaxf(fmaf(y0.z, sc0.z, sh0.z), 0.f);
        a0.w += c * fmaxf(fmaf(y0.w, sc0.w, sh0.w), 0.f);
        a1.x += c * fmaxf(fmaf(y1.x, sc1.x, sh1.x), 0.f);
        a1.y += c * fmaxf(fmaf(y1.y, sc1.y, sh1.y), 0.f);
        a1.z += c * fmaxf(fmaf(y1.z, sc1.z, sh1.z), 0.f);
        a1.w += c * fmaxf(fmaf(y1.w, sc1.w, sh1.w), 0.f);
    }
    ((float4*)outp)[(size_t)warp * 64 + f0] = a0;
    ((float4*)outp)[(size_t)warp * 64 + f1] = a1;
}

__global__ void __launch_bounds__(256) k_agg_z64(const float* __restrict__ h,
                                                 const int* __restrict__ rowstart,
                                                 const int* __restrict__ col,
                                                 const float* __restrict__ dinv,
                                                 const float* __restrict__ bias,
                                                 float* __restrict__ zout) {
    int warp = (blockIdx.x * blockDim.x + threadIdx.x) >> 5;
    int lane = threadIdx.x & 31;
    if (warp >= Nn) return;
    float di = dinv[warp];
    int jb = rowstart[warp], je = rowstart[warp + 1];
    const float2* h2 = (const float2*)h;  // 32 float2 per row
    float cs = di * di;
    float2 x = h2[(size_t)warp * 32 + lane];
    float2 a = make_float2(cs * x.x, cs * x.y);
    for (int j = jb; j < je; ++j) {
        int s = col[j];
        float c = di * dinv[s];
        float2 y = h2[(size_t)s * 32 + lane];
        a.x += c * y.x; a.y += c * y.y;
    }
    float2 b = *(const float2*)(bias + lane * 2);
    a.x += b.x; a.y += b.y;
    ((float2*)zout)[(size_t)warp * 32 + lane] = a;
}

// ===================== mma.sync bf16 GEMM (3-pass hi/lo, reg prefetch) =======
// BNA: BN finalize computed inline from raw stats (bnA/bnsqA/gammaA/betaA),
// then relu(a*sc+sh) applied during staging.
__device__ __forceinline__ void mma16816(float* acc, const uint32_t* a, const uint32_t* b) {
    asm volatile(
        "mma.sync.aligned.m16n8k16.row.col.f32.bf16.bf16.f32 "
        "{%0,%1,%2,%3}, {%4,%5,%6,%7}, {%8,%9}, {%0,%1,%2,%3};"
        : "+f"(acc[0]), "+f"(acc[1]), "+f"(acc[2]), "+f"(acc[3])
        : "r"(a[0]), "r"(a[1]), "r"(a[2]), "r"(a[3]), "r"(b[0]), "r"(b[1]));
}

template <int KT, int NT, bool HAS_BIAS, bool STATS, bool BNA>
__global__ void __launch_bounds__(256, 2) k_mma(const float* __restrict__ A,
                                                const uint32_t* __restrict__ Bp,
                                                const float* __restrict__ bias,
                                                float* __restrict__ C,
                                                float* __restrict__ bnsum,
                                                float* __restrict__ bnsumsq,
                                                const float* __restrict__ bnA,
                                                const float* __restrict__ bnsqA,
                                                const float* __restrict__ gammaA,
                                                const float* __restrict__ betaA) {
    constexpr int M = Nn;
    constexpr int NCH = KT / 32;
    __shared__ __nv_bfloat16 Ahi[128][40];
    __shared__ __nv_bfloat16 Alo[128][40];
    __shared__ __nv_bfloat16 Bhi[64][40];
    __shared__ __nv_bfloat16 Blo[64][40];
    __shared__ float s_scA[BNA ? KT : 1];
    __shared__ float s_shA[BNA ? KT : 1];

    int tid = threadIdx.x;
    int wid = tid >> 5, lane = tid & 31;
    int g = lane >> 2, tig = lane & 3;
    int warp_m = wid & 3, warp_n = wid >> 2;
    int bm = blockIdx.y * 128, bn = blockIdx.x * 64;

    if (BNA) {
        float invM = 1.f / (float)Nn;
        for (int c = tid; c < KT; c += 256) {
            float m = bnA[c] * invM;
            float var = fmaxf(bnsqA[c] * invM - m * m, 0.f);
            float sc = gammaA[c] * rsqrtf(var + EPSB);
            s_scA[c] = sc;
            s_shA[c] = betaA[c] - m * sc;
        }
        __syncthreads();
    }

    const int rA = tid >> 1;
    const int koffA = (tid & 1) * 16;
    const bool validA = (bm + rA) < M;
    const int nB = tid >> 2;
    const int koffB = (tid & 3) * 8;

    float acc[2][4][4];
#pragma unroll
    for (int mt = 0; mt < 2; ++mt)
#pragma unroll
        for (int nt = 0; nt < 4; ++nt)
#pragma unroll
            for (int i = 0; i < 4; ++i) acc[mt][nt][i] = 0.f;

    float va[16];
    uint32_t vb[8];

    // ---- prefetch chunk 0 into registers
    {
        if (validA) {
            const float4* src = (const float4*)(A + (size_t)(bm + rA) * KT + koffA);
#pragma unroll
            for (int q = 0; q < 4; ++q) *(float4*)&va[q * 4] = src[q];
        } else {
#pragma unroll
            for (int q = 0; q < 16; ++q) va[q] = 0.f;
        }
        const uint4* srcB = (const uint4*)(Bp + (size_t)(bn + nB) * KT + koffB);
        uint4 v0 = srcB[0], v1 = srcB[1];
        vb[0] = v0.x; vb[1] = v0.y; vb[2] = v0.z; vb[3] = v0.w;
        vb[4] = v1.x; vb[5] = v1.y; vb[6] = v1.z; vb[7] = v1.w;
    }

    for (int ch = 0; ch < NCH; ++ch) {
        const int k0 = ch * 32;
        // ---- store staged registers to smem (BN? + hi/lo split for A)
        {
            float v[16];
#pragma unroll
            for (int q = 0; q < 16; ++q) v[q] = va[q];
            if (BNA) {
                const float4* scp = (const float4*)(s_scA + k0 + koffA);
                const float4* shp = (const float4*)(s_shA + k0 + koffA);
#pragma unroll
                for (int q = 0; q < 4; ++q) {
                    float4 sc = scp[q], sh = shp[q];
                    v[q * 4 + 0] = fmaxf(fmaf(v[q * 4 + 0], sc.x, sh.x), 0.f);
                    v[q * 4 + 1] = fmaxf(fmaf(v[q * 4 + 1], sc.y, sh.y), 0.f);
                    v[q * 4 + 2] = fmaxf(fmaf(v[q * 4 + 2], sc.z, sh.z), 0.f);
                    v[q * 4 + 3] = fmaxf(fmaf(v[q * 4 + 3], sc.w, sh.w), 0.f);
                }
            }
#pragma unroll
            for (int i = 0; i < 16; i += 2) {
                __nv_bfloat16 h0 = __float2bfloat16(v[i]);
                __nv_bfloat16 h1 = __float2bfloat16(v[i + 1]);
                __nv_bfloat16 l0 = __float2bfloat16(v[i] - __bfloat162float(h0));
                __nv_bfloat16 l1 = __float2bfloat16(v[i + 1] - __bfloat162float(h1));
                *(uint32_t*)&Ahi[rA][koffA + i] =
                    (uint32_t)__bfloat16_as_ushort(h0) | ((uint32_t)__bfloat16_as_ushort(h1) << 16);
                *(uint32_t*)&Alo[rA][koffA + i] =
                    (uint32_t)__bfloat16_as_ushort(l0) | ((uint32_t)__bfloat16_as_ushort(l1) << 16);
            }
#pragma unroll
            for (int i = 0; i < 8; i += 2) {
                uint32_t p0 = vb[i], p1 = vb[i + 1];
                *(uint32_t*)&Bhi[nB][koffB + i] = (p0 & 0xFFFFu) | (p1 << 16);
                *(uint32_t*)&Blo[nB][koffB + i] = (p0 >> 16) | (p1 & 0xFFFF0000u);
            }
        }
        __syncthreads();

        // ---- prefetch next chunk (overlaps MMA phase)
        if (ch + 1 < NCH) {
            const int k1 = (ch + 1) * 32;
            if (validA) {
                const float4* src = (const float4*)(A + (size_t)(bm + rA) * KT + k1 + koffA);
#pragma unroll
                for (int q = 0; q < 4; ++q) *(float4*)&va[q * 4] = src[q];
            }
            const uint4* srcB = (const uint4*)(Bp + (size_t)(bn + nB) * KT + k1 + koffB);
            uint4 v0 = srcB[0], v1 = srcB[1];
            vb[0] = v0.x; vb[1] = v0.y; vb[2] = v0.z; vb[3] = v0.w;
            vb[4] = v1.x; vb[5] = v1.y; vb[6] = v1.z; vb[7] = v1.w;
        }

        // ---- MMA phase
#pragma unroll
        for (int kk = 0; kk < 32; kk += 16) {
            uint32_t ah[2][4], al[2][4], bh[4][2], bl[4][2];
            int cA = kk + tig * 2;
#pragma unroll
            for (int mt = 0; mt < 2; ++mt) {
                int r0 = warp_m * 32 + mt * 16 + g;
                ah[mt][0] = *(const uint32_t*)&Ahi[r0][cA];
                ah[mt][1] = *(const uint32_t*)&Ahi[r0 + 8][cA];
                ah[mt][2] = *(const uint32_t*)&Ahi[r0][cA + 8];
                ah[mt][3] = *(const uint32_t*)&Ahi[r0 + 8][cA + 8];
                al[mt][0] = *(const uint32_t*)&Alo[r0][cA];
                al[mt][1] = *(const uint32_t*)&Alo[r0 + 8][cA];
                al[mt][2] = *(const uint32_t*)&Alo[r0][cA + 8];
                al[mt][3] = *(const uint32_t*)&Alo[r0 + 8][cA + 8];
            }
#pragma unroll
            for (int nt = 0; nt < 4; ++nt) {
                int n0 = warp_n * 32 + nt * 8 + g;
                bh[nt][0] = *(const uint32_t*)&Bhi[n0][cA];
                bh[nt][1] = *(const uint32_t*)&Bhi[n0][cA + 8];
                bl[nt][0] = *(const uint32_t*)&Blo[n0][cA];
                bl[nt][1] = *(const uint32_t*)&Blo[n0][cA + 8];
            }
#pragma unroll
            for (int mt = 0; mt < 2; ++mt)
#pragma unroll
                for (int nt = 0; nt < 4; ++nt) {
                    mma16816(acc[mt][nt], ah[mt], bh[nt]);
                    mma16816(acc[mt][nt], ah[mt], bl[nt]);
                    mma16816(acc[mt][nt], al[mt], bh[nt]);
                }
        }
        __syncthreads();
    }

    // ---- epilogue: write C (+bias)
#pragma unroll
    for (int mt = 0; mt < 2; ++mt) {
        int r0 = bm + warp_m * 32 + mt * 16 + g;
#pragma unroll
        for (int nt = 0; nt < 4; ++nt) {
            int cc = bn + warp_n * 32 + nt * 8 + tig * 2;
            float b0 = 0.f, b1 = 0.f;
            if (HAS_BIAS) { b0 = bias[cc]; b1 = bias[cc + 1]; }
            if (r0 < M) {
                float2 v = make_float2(acc[mt][nt][0] + b0, acc[mt][nt][1] + b1);
                *(float2*)(C + (size_t)r0 * NT + cc) = v;
            }
            if (r0 + 8 < M) {
                float2 v = make_float2(acc[mt][nt][2] + b0, acc[mt][nt][3] + b1);
                *(float2*)(C + (size_t)(r0 + 8) * NT + cc) = v;
            }
        }
    }

    // ---- fused BN statistics
    if (STATS) {
#pragma unroll
        for (int nt = 0; nt < 4; ++nt) {
            float s0 = 0.f, s1 = 0.f, q0 = 0.f, q1 = 0.f;
#pragma unroll
            for (int mt = 0; mt < 2; ++mt) {
                int r0 = bm + warp_m * 32 + mt * 16 + g;
                if (r0 < M) {
                    float v0 = acc[mt][nt][0], v1 = acc[mt][nt][1];
                    s0 += v0; q0 += v0 * v0;
                    s1 += v1; q1 += v1 * v1;
                }
                if (r0 + 8 < M) {
                    float v0 = acc[mt][nt][2], v1 = acc[mt][nt][3];
                    s0 += v0; q0 += v0 * v0;
                    s1 += v1; q1 += v1 * v1;
                }
            }
#pragma unroll
            for (int o = 4; o < 32; o <<= 1) {
                s0 += __shfl_xor_sync(0xFFFFFFFFu, s0, o);
                s1 += __shfl_xor_sync(0xFFFFFFFFu, s1, o);
                q0 += __shfl_xor_sync(0xFFFFFFFFu, q0, o);
                q1 += __shfl_xor_sync(0xFFFFFFFFu, q1, o);
            }
            if (lane < 4) {
                int cc = bn + warp_n * 32 + nt * 8 + lane * 2;
                atomicAdd(&bnsum[cc], s0);
                atomicAdd(&bnsum[cc + 1], s1);
                atomicAdd(&bnsumsq[cc], q0);
                atomicAdd(&bnsumsq[cc + 1], q1);
            }
        }
    }
}

// ===================== host orchestration ====================================
template <int KT, int NT, bool HAS_BIAS, bool STATS, bool BNA>
static void launch_mma(const float* A, const uint32_t* Bp, const float* bias,
                       float* C, float* bnsum, float* bnsumsq,
                       const float* bnA, const float* bnsqA,
                       const float* gammaA, const float* betaA) {
    dim3 grid(NT / 64, (Nn + 127) / 128);
    k_mma<KT, NT, HAS_BIAS, STATS, BNA><<<grid, 256>>>(A, Bp, bias, C, bnsum, bnsumsq,
                                                       bnA, bnsqA, gammaA, betaA);
}

extern "C" void kernel_launch(void* const* d_in, const int* in_sizes, int n_in,
                              void* d_out, int out_size) {
    const float* x  = (const float*)d_in[0];
    const void*  ei = d_in[1];
    const float* W1 = (const float*)d_in[2];
    const float* g1 = (const float*)d_in[4];
    const float* be1 = (const float*)d_in[5];
    const float* W2 = (const float*)d_in[6];
    const float* g2 = (const float*)d_in[8];
    const float* be2 = (const float*)d_in[9];
    const float* W3 = (const float*)d_in[10];
    const float* b3 = (const float*)d_in[11];
    const float* dW1 = (const float*)d_in[12];
    const float* dg1 = (const float*)d_in[14];
    const float* dbe1 = (const float*)d_in[15];
    const float* dW2 = (const float*)d_in[16];
    const float* dg2 = (const float*)d_in[18];
    const float* dbe2 = (const float*)d_in[19];
    const float* dW3 = (const float*)d_in[20];
    const float* db3 = (const float*)d_in[21];

    float* out  = (float*)d_out;
    float* xhat = out;                           // [Nn, INC]
    float* zout = out + (size_t)Nn * INC;        // [Nn, LC]

    float *bufA, *bufB, *zbuf, *dinv, *bnsum, *bnsumsq;
    uint32_t *wsp;
    int *cnt, *rowstart, *wr, *colarr, *partial;
    cudaGetSymbolAddress((void**)&bufA, g_bufA);
    cudaGetSymbolAddress((void**)&bufB, g_bufB);
    cudaGetSymbolAddress((void**)&zbuf, g_zbuf);
    cudaGetSymbolAddress((void**)&wsp, g_wsplit);
    cudaGetSymbolAddress((void**)&dinv, g_dinv);
    cudaGetSymbolAddress((void**)&cnt, g_cnt);
    cudaGetSymbolAddress((void**)&rowstart, g_rowstart);
    cudaGetSymbolAddress((void**)&wr, g_wr);
    cudaGetSymbolAddress((void**)&colarr, g_col);
    cudaGetSymbolAddress((void**)&partial, g_partial);
    cudaGetSymbolAddress((void**)&bnsum, g_bnsum);
    cudaGetSymbolAddress((void**)&bnsumsq, g_bnsumsq);

    // ---- zero+detect + CSR build (parallel scan, dinv fused) ----
    k_zero_detect<<<(Nn + 255) / 256, 256>>>(cnt, bnsum, bnsumsq, (const long long*)ei);
    k_hist<<<(Ed + 255) / 256, 256>>>(ei, cnt);
    k_blocksum<<<SCAN_NB, 1024>>>(cnt, partial);
    k_scanpartial<<<1, 32>>>(partial, rowstart + Nn);
    k_scanlocal<<<SCAN_NB, 1024>>>(cnt, partial, rowstart, wr, dinv);
    k_scatter<<<(Ed + 255) / 256, 256>>>(ei, wr, colarr);

    // ---- weight transpose + split (one launch) ----
    k_wsplit_all<<<(229376 + 255) / 256, 256>>>(W1, W2, W3, dW1, dW2, dW3, wsp);

    const int aggBlocks = (Nn * 32 + 255) / 256;

    // ---- encoder layer 1:  raw1 = agg(x) @ W1 ; stats0 ----
    k_agg128<<<aggBlocks, 256>>>(x, rowstart, colarr, dinv, bufB);
    launch_mma<INC, HC, false, true, false>(bufB, wsp + WOFF_1, nullptr, bufA,
                                            bnsum, bnsumsq,
                                            nullptr, nullptr, nullptr, nullptr);

    // ---- encoder layer 2:  raw2 = agg(BNrelu(raw1)) @ W2 ; stats1 ----
    k_agg256_bn<<<aggBlocks, 256>>>(bufA, rowstart, colarr, dinv,
                                    bnsum, bnsumsq, g1, be1, bufB);
    launch_mma<HC, HC, false, true, false>(bufB, wsp + WOFF_2, nullptr, bufA,
                                           bnsum + HC, bnsumsq + HC,
                                           nullptr, nullptr, nullptr, nullptr);

    // ---- encoder layer 3:  z = agg( BNrelu(raw2) @ W3 ) + b3 ----
    launch_mma<HC, LC, false, false, true>(bufA, wsp + WOFF_3, nullptr, zbuf,
                                           nullptr, nullptr,
                                           bnsum + HC, bnsumsq + HC, g2, be2);
    k_agg_z64<<<aggBlocks, 256>>>(zbuf, rowstart, colarr, dinv, b3, zout);

    // ---- decoder ----
    launch_mma<LC, HC, false, true, false>(zout, wsp + WOFF_4, nullptr, bufA,
                                           bnsum + 2 * HC, bnsumsq + 2 * HC,
                                           nullptr, nullptr, nullptr, nullptr);

    launch_mma<HC, HC, false, true, true>(bufA, wsp + WOFF_5, nullptr, bufB,
                                          bnsum + 3 * HC, bnsumsq + 3 * HC,
                                          bnsum + 2 * HC, bnsumsq + 2 * HC, dg1, dbe1);

    launch_mma<HC, INC, true, false, true>(bufB, wsp + WOFF_6, db3, xhat,
                                           nullptr, nullptr,
                                           bnsum + 3 * HC, bnsumsq + 3 * HC, dg2, dbe2);
}